// round 1
// baseline (speedup 1.0000x reference)
#include <cuda_runtime.h>
#include <cstdint>

// Problem: fused Linear + 3x channel-weighted visualization reductions.
// Inputs (metadata order):
//   0: concat_gap [16,448] f32
//   1: out1 [16,64,15,64,64] f32   (S1 = 61440)
//   2: out2 [16,128,8,32,32] f32   (S2 = 8192)
//   3: out3 [16,256,4,16,16] f32   (S3 = 1024)
//   4: weight [3,448] f32
//   5: bias [3] f32
// Output (concatenated): fc_out[16,3] (48) | vis1 (983040) | vis2 (131072) | vis3 (16384)

#define B 16
#define KDIM 448

// region geometry (in float4 vectors)
#define SV1 15360   // 61440/4
#define SV2 2048    // 8192/4
#define SV3 256     // 1024/4
#define NBLK1 960   // 16*15360/256
#define NBLK2 128   // 16*2048/256
#define NBLK3 16    // 16*256/256

#define OUT_FC   0
#define OUT_V1   48
#define OUT_V2   (48 + 983040)
#define OUT_V3   (48 + 983040 + 131072)

template<int C, int SV>
__device__ __forceinline__ void vis_region(const float* __restrict__ src,
                                           float* __restrict__ dst,
                                           const float* __restrict__ weight,
                                           int woff, int relblk)
{
    __shared__ float w[C];
    int tid = threadIdx.x;
    if (tid < C) {
        w[tid] = 0.5f * (weight[woff + tid] + weight[KDIM + woff + tid]);
    }
    __syncthreads();

    // global float4 output index in this region
    int64_t v  = (int64_t)relblk * blockDim.x + tid;
    int     b  = (int)(v / SV);
    int     sv = (int)(v % SV);

    const float4* in = reinterpret_cast<const float4*>(src)
                       + (int64_t)b * C * SV + sv;

    float4 acc = make_float4(0.f, 0.f, 0.f, 0.f);
#pragma unroll 16
    for (int c = 0; c < C; ++c) {
        float4 x = in[(int64_t)c * SV];
        float wc = w[c];
        acc.x += wc * x.x;
        acc.y += wc * x.y;
        acc.z += wc * x.z;
        acc.w += wc * x.w;
    }
    reinterpret_cast<float4*>(dst)[v] = acc;
}

__global__ void __launch_bounds__(256)
fused_vis_kernel(const float* __restrict__ gap,
                 const float* __restrict__ out1,
                 const float* __restrict__ out2,
                 const float* __restrict__ out3,
                 const float* __restrict__ weight,
                 const float* __restrict__ bias,
                 float* __restrict__ dout)
{
    int blk = blockIdx.x;
    if (blk < NBLK1) {
        vis_region<64, SV1>(out1, dout + OUT_V1, weight, 0, blk);
    } else if (blk < NBLK1 + NBLK2) {
        vis_region<128, SV2>(out2, dout + OUT_V2, weight, 64, blk - NBLK1);
    } else if (blk < NBLK1 + NBLK2 + NBLK3) {
        vis_region<256, SV3>(out3, dout + OUT_V3, weight, 192, blk - NBLK1 - NBLK2);
    } else {
        // fc block: fc_out[b][j] = gap[b] . weight[j] + bias[j]
        int t = threadIdx.x;
        if (t < B * 3) {
            int b = t / 3;
            int j = t % 3;
            const float4* g = reinterpret_cast<const float4*>(gap + b * KDIM);
            const float4* wv = reinterpret_cast<const float4*>(weight + j * KDIM);
            float acc = 0.f;
#pragma unroll 8
            for (int k = 0; k < KDIM / 4; ++k) {
                float4 a = g[k];
                float4 ww = wv[k];
                acc += a.x * ww.x + a.y * ww.y + a.z * ww.z + a.w * ww.w;
            }
            dout[OUT_FC + t] = acc + bias[j];
        }
    }
}

extern "C" void kernel_launch(void* const* d_in, const int* in_sizes, int n_in,
                              void* d_out, int out_size)
{
    const float* gap    = (const float*)d_in[0];
    const float* out1   = (const float*)d_in[1];
    const float* out2   = (const float*)d_in[2];
    const float* out3   = (const float*)d_in[3];
    const float* weight = (const float*)d_in[4];
    const float* bias   = (const float*)d_in[5];
    float* dout = (float*)d_out;

    int nblocks = NBLK1 + NBLK2 + NBLK3 + 1;
    fused_vis_kernel<<<nblocks, 256>>>(gap, out1, out2, out3, weight, bias, dout);
}

// round 2
// speedup vs baseline: 1.1173x; 1.1173x over previous
#include <cuda_runtime.h>

// Fused Linear + 3x channel-weighted reductions, dynamically scheduled.
// Inputs: 0 gap[16,448], 1 out1[16,64,15,64,64], 2 out2[16,128,8,32,32],
//         3 out3[16,256,4,16,16], 4 weight[3,448], 5 bias[3]
// Output: fc[48] | vis1[983040] | vis2[131072] | vis3[16384]  (float)

#define BATCH 16
#define KDIM  448

#define SV1 15360   // spatial float4s per batch, region1
#define SV2 2048
#define SV3 256

// tiles: 64 float4 outputs each, 4-way C split across 256 threads
#define NT3 64      // 16*256/64
#define NT2 512     // 16*2048/64
#define NT1 3840    // 16*15360/64
#define NTILES (NT3 + NT2 + NT1)   // 4416

#define OUT_FC 0
#define OUT_V1 48
#define OUT_V2 (48 + 983040)
#define OUT_V3 (48 + 983040 + 131072)

#define GRID_MAIN 592   // 4 blocks/SM * 148 SMs — single resident wave

__device__ int g_ctr;

// Tiny init: reset work counter + compute fc_out (16x3 GEMV over K=448).
__global__ void init_kernel(const float* __restrict__ gap,
                            const float* __restrict__ weight,
                            const float* __restrict__ bias,
                            float* __restrict__ dout)
{
    if (threadIdx.x == 0) g_ctr = 0;
    int t = threadIdx.x;
    if (t < BATCH * 3) {
        int b = t / 3, j = t % 3;
        const float4* g4 = reinterpret_cast<const float4*>(gap + b * KDIM);
        const float4* w4 = reinterpret_cast<const float4*>(weight + j * KDIM);
        float acc = 0.f;
#pragma unroll 8
        for (int k = 0; k < KDIM / 4; ++k) {
            float4 a = g4[k], w = w4[k];
            acc += a.x * w.x + a.y * w.y + a.z * w.z + a.w * w.w;
        }
        dout[OUT_FC + t] = acc + bias[j];
    }
}

// Process one tile: 64 float4 outputs, threads split C into 4 groups.
// C = channels, SV = spatial float4s per batch, CC = C/4 per group.
template<int C, int SV>
__device__ __forceinline__ void do_tile(const float* __restrict__ src,
                                        float* __restrict__ dst,
                                        const float* __restrict__ wsm, // combined weights for this region
                                        float4* __restrict__ part,
                                        int lt)
{
    constexpr int CC = C / 4;
    int tid = threadIdx.x;
    int o = tid & 63;
    int g = tid >> 6;           // 0..3 channel group
    int v = lt * 64 + o;        // float4 output index within region
    int b = v / SV;
    int sv = v - b * SV;

    const float4* in = reinterpret_cast<const float4*>(src)
                       + b * (C * SV) + sv + (g * CC) * SV;
    const float* wg = wsm + g * CC;

    float4 a0 = make_float4(0.f, 0.f, 0.f, 0.f);
    float4 a1 = make_float4(0.f, 0.f, 0.f, 0.f);
#pragma unroll
    for (int c = 0; c < CC; c += 8) {
        float4 x0 = in[(c + 0) * SV];
        float4 x1 = in[(c + 1) * SV];
        float4 x2 = in[(c + 2) * SV];
        float4 x3 = in[(c + 3) * SV];
        float4 x4 = in[(c + 4) * SV];
        float4 x5 = in[(c + 5) * SV];
        float4 x6 = in[(c + 6) * SV];
        float4 x7 = in[(c + 7) * SV];
        float w0 = wg[c + 0], w1 = wg[c + 1], w2 = wg[c + 2], w3 = wg[c + 3];
        float w4 = wg[c + 4], w5 = wg[c + 5], w6 = wg[c + 6], w7 = wg[c + 7];
        a0.x += w0 * x0.x; a0.y += w0 * x0.y; a0.z += w0 * x0.z; a0.w += w0 * x0.w;
        a1.x += w1 * x1.x; a1.y += w1 * x1.y; a1.z += w1 * x1.z; a1.w += w1 * x1.w;
        a0.x += w2 * x2.x; a0.y += w2 * x2.y; a0.z += w2 * x2.z; a0.w += w2 * x2.w;
        a1.x += w3 * x3.x; a1.y += w3 * x3.y; a1.z += w3 * x3.z; a1.w += w3 * x3.w;
        a0.x += w4 * x4.x; a0.y += w4 * x4.y; a0.z += w4 * x4.z; a0.w += w4 * x4.w;
        a1.x += w5 * x5.x; a1.y += w5 * x5.y; a1.z += w5 * x5.z; a1.w += w5 * x5.w;
        a0.x += w6 * x6.x; a0.y += w6 * x6.y; a0.z += w6 * x6.z; a0.w += w6 * x6.w;
        a1.x += w7 * x7.x; a1.y += w7 * x7.y; a1.z += w7 * x7.z; a1.w += w7 * x7.w;
    }
    float4 acc = make_float4(a0.x + a1.x, a0.y + a1.y, a0.z + a1.z, a0.w + a1.w);

    if (g != 0) part[(g - 1) * 64 + o] = acc;
    __syncthreads();
    if (g == 0) {
        float4 p0 = part[o], p1 = part[64 + o], p2 = part[128 + o];
        acc.x += p0.x + p1.x + p2.x;
        acc.y += p0.y + p1.y + p2.y;
        acc.z += p0.z + p1.z + p2.z;
        acc.w += p0.w + p1.w + p2.w;
        reinterpret_cast<float4*>(dst)[v] = acc;
    }
}

__global__ void __launch_bounds__(256, 4)
fused_vis_kernel(const float* __restrict__ out1,
                 const float* __restrict__ out2,
                 const float* __restrict__ out3,
                 const float* __restrict__ weight,
                 float* __restrict__ dout)
{
    __shared__ float  wsm[KDIM];     // combined 0.5*(w0+w1)
    __shared__ float4 part[192];
    __shared__ int    s_tile;

    int tid = threadIdx.x;
    for (int k = tid; k < KDIM; k += 256)
        wsm[k] = 0.5f * (weight[k] + weight[KDIM + k]);
    // sync at loop top covers wsm visibility

    for (;;) {
        if (tid == 0) s_tile = atomicAdd(&g_ctr, 1);
        __syncthreads();             // s_tile (and first-iter wsm) visible; part[] reads done
        int t = s_tile;
        if (t >= NTILES) break;

        if (t < NT3) {
            do_tile<256, SV3>(out3, dout + OUT_V3, wsm + 192, part, t);
        } else if (t < NT3 + NT2) {
            do_tile<128, SV2>(out2, dout + OUT_V2, wsm + 64, part, t - NT3);
        } else {
            do_tile<64, SV1>(out1, dout + OUT_V1, wsm, part, t - NT3 - NT2);
        }
    }
}

extern "C" void kernel_launch(void* const* d_in, const int* in_sizes, int n_in,
                              void* d_out, int out_size)
{
    const float* gap    = (const float*)d_in[0];
    const float* out1   = (const float*)d_in[1];
    const float* out2   = (const float*)d_in[2];
    const float* out3   = (const float*)d_in[3];
    const float* weight = (const float*)d_in[4];
    const float* bias   = (const float*)d_in[5];
    float* dout = (float*)d_out;

    init_kernel<<<1, 64>>>(gap, weight, bias, dout);
    fused_vis_kernel<<<GRID_MAIN, 256>>>(out1, out2, out3, weight, dout);
}

// round 3
// speedup vs baseline: 1.2190x; 1.0910x over previous
#include <cuda_runtime.h>

// Single fused kernel: Linear (16x3 GEMV) + 3x channel-weighted reductions.
// Persistent grid, warp-autonomous dynamic tiles, self-resetting counters.
// Inputs: 0 gap[16,448], 1 out1[16,64,15,64,64], 2 out2[16,128,8,32,32],
//         3 out3[16,256,4,16,16], 4 weight[3,448], 5 bias[3]
// Output: fc[48] | vis1[983040] | vis2[131072] | vis3[16384]  (float)

#define BATCH 16
#define KDIM  448

#define SV1 15360   // spatial float4s per batch image
#define SV2 2048
#define SV3 256

// warp tiles: 32 float4 outputs each. fc is tile 0; heavy regions first.
#define NW3 128     // 16*256/32
#define NW2 1024    // 16*2048/32
#define NW1 7680    // 16*15360/32
#define T3_BEG 1
#define T2_BEG (1 + NW3)
#define T1_BEG (1 + NW3 + NW2)
#define TOTAL_WTILES (1 + NW3 + NW2 + NW1)   // 8833

#define OUT_FC 0
#define OUT_V1 48
#define OUT_V2 (48 + 983040)
#define OUT_V3 (48 + 983040 + 131072)

#define GRID_MAIN 592                      // 4 blocks/SM * 148 SMs, single wave
#define TOTAL_WARPS (GRID_MAIN * 8)

__device__ int g_ctr  = 0;
__device__ int g_done = 0;

// One warp tile: 32 consecutive float4 outputs, full C reduction per thread.
template<int C, int SV>
__device__ __forceinline__ void warp_tile(const float* __restrict__ src,
                                          float* __restrict__ dst,
                                          const float* __restrict__ w,
                                          int lt)
{
    int lane = threadIdx.x & 31;
    int v  = lt * 32 + lane;      // float4 output index within region
    int b  = v / SV;
    int sv = v - b * SV;

    const float4* in = reinterpret_cast<const float4*>(src) + b * (C * SV) + sv;

    float4 a0 = make_float4(0.f, 0.f, 0.f, 0.f);
    float4 a1 = make_float4(0.f, 0.f, 0.f, 0.f);
#pragma unroll 1
    for (int c = 0; c < C; c += 8) {
        float4 x0 = in[(c + 0) * SV];
        float4 x1 = in[(c + 1) * SV];
        float4 x2 = in[(c + 2) * SV];
        float4 x3 = in[(c + 3) * SV];
        float4 x4 = in[(c + 4) * SV];
        float4 x5 = in[(c + 5) * SV];
        float4 x6 = in[(c + 6) * SV];
        float4 x7 = in[(c + 7) * SV];
        float w0 = w[c + 0], w1 = w[c + 1], w2 = w[c + 2], w3 = w[c + 3];
        float w4 = w[c + 4], w5 = w[c + 5], w6 = w[c + 6], w7 = w[c + 7];
        a0.x += w0 * x0.x; a0.y += w0 * x0.y; a0.z += w0 * x0.z; a0.w += w0 * x0.w;
        a1.x += w1 * x1.x; a1.y += w1 * x1.y; a1.z += w1 * x1.z; a1.w += w1 * x1.w;
        a0.x += w2 * x2.x; a0.y += w2 * x2.y; a0.z += w2 * x2.z; a0.w += w2 * x2.w;
        a1.x += w3 * x3.x; a1.y += w3 * x3.y; a1.z += w3 * x3.z; a1.w += w3 * x3.w;
        a0.x += w4 * x4.x; a0.y += w4 * x4.y; a0.z += w4 * x4.z; a0.w += w4 * x4.w;
        a1.x += w5 * x5.x; a1.y += w5 * x5.y; a1.z += w5 * x5.z; a1.w += w5 * x5.w;
        a0.x += w6 * x6.x; a0.y += w6 * x6.y; a0.z += w6 * x6.z; a0.w += w6 * x6.w;
        a1.x += w7 * x7.x; a1.y += w7 * x7.y; a1.z += w7 * x7.z; a1.w += w7 * x7.w;
    }
    float4 acc = make_float4(a0.x + a1.x, a0.y + a1.y, a0.z + a1.z, a0.w + a1.w);
    reinterpret_cast<float4*>(dst)[v] = acc;
}

__global__ void __launch_bounds__(256, 4)
fused_all_kernel(const float* __restrict__ gap,
                 const float* __restrict__ out1,
                 const float* __restrict__ out2,
                 const float* __restrict__ out3,
                 const float* __restrict__ weight,
                 const float* __restrict__ bias,
                 float* __restrict__ dout)
{
    __shared__ float wsm[KDIM];   // combined 0.5*(w0+w1)
    int tid  = threadIdx.x;
    int lane = tid & 31;

    for (int k = tid; k < KDIM; k += 256)
        wsm[k] = 0.5f * (weight[k] + weight[KDIM + k]);
    __syncthreads();

    for (;;) {
        int t;
        if (lane == 0) t = atomicAdd(&g_ctr, 1);
        t = __shfl_sync(0xffffffffu, t, 0);
        if (t >= TOTAL_WTILES) break;

        if (t >= T1_BEG) {
            warp_tile<64, SV1>(out1, dout + OUT_V1, wsm, t - T1_BEG);
        } else if (t >= T2_BEG) {
            warp_tile<128, SV2>(out2, dout + OUT_V2, wsm + 64, t - T2_BEG);
        } else if (t >= T3_BEG) {
            warp_tile<256, SV3>(out3, dout + OUT_V3, wsm + 192, t - T3_BEG);
        } else {
            // fc tile: fc[b][j] = gap[b] . weight[j] + bias[j]  (48 outputs)
            for (int o = lane; o < BATCH * 3; o += 32) {
                int b = o / 3, j = o % 3;
                const float4* g4 = reinterpret_cast<const float4*>(gap + b * KDIM);
                const float4* w4 = reinterpret_cast<const float4*>(weight + j * KDIM);
                float acc = 0.f;
#pragma unroll 8
                for (int k = 0; k < KDIM / 4; ++k) {
                    float4 a = g4[k], w = w4[k];
                    acc += a.x * w.x + a.y * w.y + a.z * w.z + a.w * w.w;
                }
                dout[OUT_FC + o] = acc + bias[j];
            }
        }
    }

    // self-reset: the last warp out restores counters for the next graph replay.
    if (lane == 0) {
        __threadfence();
        int d = atomicAdd(&g_done, 1);
        if (d == TOTAL_WARPS - 1) {
            g_ctr  = 0;
            g_done = 0;
            __threadfence();
        }
    }
}

extern "C" void kernel_launch(void* const* d_in, const int* in_sizes, int n_in,
                              void* d_out, int out_size)
{
    const float* gap    = (const float*)d_in[0];
    const float* out1   = (const float*)d_in[1];
    const float* out2   = (const float*)d_in[2];
    const float* out3   = (const float*)d_in[3];
    const float* weight = (const float*)d_in[4];
    const float* bias   = (const float*)d_in[5];
    float* dout = (float*)d_out;

    fused_all_kernel<<<GRID_MAIN, 256>>>(gap, out1, out2, out3, weight, bias, dout);
}

// round 4
// speedup vs baseline: 1.4003x; 1.1488x over previous
#include <cuda_runtime.h>

// Single fused persistent kernel: Linear (16x3 GEMV) + 3x channel-weighted
// reductions. Block-level dynamic tiles (64 float4 outputs, 4-way C split),
// full-unroll load batching for high MLP, self-resetting counters.
// Inputs: 0 gap[16,448], 1 out1[16,64,15,64,64], 2 out2[16,128,8,32,32],
//         3 out3[16,256,4,16,16], 4 weight[3,448], 5 bias[3]
// Output: fc[48] | vis1[983040] | vis2[131072] | vis3[16384]  (float)

#define BATCH 16
#define KDIM  448

#define SV1 15360   // spatial float4s per batch image
#define SV2 2048
#define SV3 256

// block tiles: 64 float4 outputs each, 4-way C split across 256 threads.
// tile 0 = fc; then heavy-first: region3 (256KB/tile), region2 (128KB), region1 (64KB).
#define NT3 64      // 16*256/64
#define NT2 512     // 16*2048/64
#define NT1 3840    // 16*15360/64
#define T3_BEG 1
#define T2_BEG (1 + NT3)
#define T1_BEG (1 + NT3 + NT2)
#define TOTAL_TILES (1 + NT3 + NT2 + NT1)   // 4417

#define OUT_FC 0
#define OUT_V1 48
#define OUT_V2 (48 + 983040)
#define OUT_V3 (48 + 983040 + 131072)

#define GRID_MAIN 592   // 4 blocks/SM * 148 SMs — single resident wave

__device__ int g_ctr  = 0;
__device__ int g_done = 0;

// One block tile: 64 float4 outputs, threads split C into 4 groups.
template<int C, int SV>
__device__ __forceinline__ void do_tile(const float* __restrict__ src,
                                        float* __restrict__ dst,
                                        const float* __restrict__ wsm,
                                        float4* __restrict__ part,
                                        int lt)
{
    constexpr int CC = C / 4;
    int tid = threadIdx.x;
    int o = tid & 63;
    int g = tid >> 6;           // 0..3 channel group
    int v = lt * 64 + o;        // float4 output index within region
    int b = v / SV;
    int sv = v - b * SV;

    const float4* in = reinterpret_cast<const float4*>(src)
                       + b * (C * SV) + sv + (g * CC) * SV;
    const float* wg = wsm + g * CC;

    float4 a0 = make_float4(0.f, 0.f, 0.f, 0.f);
    float4 a1 = make_float4(0.f, 0.f, 0.f, 0.f);
#pragma unroll
    for (int c = 0; c < CC; c += 8) {
        float4 x0 = in[(c + 0) * SV];
        float4 x1 = in[(c + 1) * SV];
        float4 x2 = in[(c + 2) * SV];
        float4 x3 = in[(c + 3) * SV];
        float4 x4 = in[(c + 4) * SV];
        float4 x5 = in[(c + 5) * SV];
        float4 x6 = in[(c + 6) * SV];
        float4 x7 = in[(c + 7) * SV];
        float w0 = wg[c + 0], w1 = wg[c + 1], w2 = wg[c + 2], w3 = wg[c + 3];
        float w4 = wg[c + 4], w5 = wg[c + 5], w6 = wg[c + 6], w7 = wg[c + 7];
        a0.x += w0 * x0.x; a0.y += w0 * x0.y; a0.z += w0 * x0.z; a0.w += w0 * x0.w;
        a1.x += w1 * x1.x; a1.y += w1 * x1.y; a1.z += w1 * x1.z; a1.w += w1 * x1.w;
        a0.x += w2 * x2.x; a0.y += w2 * x2.y; a0.z += w2 * x2.z; a0.w += w2 * x2.w;
        a1.x += w3 * x3.x; a1.y += w3 * x3.y; a1.z += w3 * x3.z; a1.w += w3 * x3.w;
        a0.x += w4 * x4.x; a0.y += w4 * x4.y; a0.z += w4 * x4.z; a0.w += w4 * x4.w;
        a1.x += w5 * x5.x; a1.y += w5 * x5.y; a1.z += w5 * x5.z; a1.w += w5 * x5.w;
        a0.x += w6 * x6.x; a0.y += w6 * x6.y; a0.z += w6 * x6.z; a0.w += w6 * x6.w;
        a1.x += w7 * x7.x; a1.y += w7 * x7.y; a1.z += w7 * x7.z; a1.w += w7 * x7.w;
    }
    float4 acc = make_float4(a0.x + a1.x, a0.y + a1.y, a0.z + a1.z, a0.w + a1.w);

    if (g != 0) part[(g - 1) * 64 + o] = acc;
    __syncthreads();
    if (g == 0) {
        float4 p0 = part[o], p1 = part[64 + o], p2 = part[128 + o];
        acc.x += p0.x + p1.x + p2.x;
        acc.y += p0.y + p1.y + p2.y;
        acc.z += p0.z + p1.z + p2.z;
        acc.w += p0.w + p1.w + p2.w;
        reinterpret_cast<float4*>(dst)[v] = acc;
    }
}

__global__ void __launch_bounds__(256, 4)
fused_all_kernel(const float* __restrict__ gap,
                 const float* __restrict__ out1,
                 const float* __restrict__ out2,
                 const float* __restrict__ out3,
                 const float* __restrict__ weight,
                 const float* __restrict__ bias,
                 float* __restrict__ dout)
{
    __shared__ float  wsm[KDIM];   // combined 0.5*(w0+w1)
    __shared__ float4 part[192];
    __shared__ int    s_tile;

    int tid = threadIdx.x;
    for (int k = tid; k < KDIM; k += 256)
        wsm[k] = 0.5f * (weight[k] + weight[KDIM + k]);
    // loop-top __syncthreads covers wsm visibility

    for (;;) {
        if (tid == 0) s_tile = atomicAdd(&g_ctr, 1);
        __syncthreads();            // s_tile + wsm visible; prior part[] reads done
        int t = s_tile;
        if (t >= TOTAL_TILES) break;

        if (t >= T1_BEG) {
            do_tile<64, SV1>(out1, dout + OUT_V1, wsm, part, t - T1_BEG);
        } else if (t >= T2_BEG) {
            do_tile<128, SV2>(out2, dout + OUT_V2, wsm + 64, part, t - T2_BEG);
        } else if (t >= T3_BEG) {
            do_tile<256, SV3>(out3, dout + OUT_V3, wsm + 192, part, t - T3_BEG);
        } else {
            // fc tile: fc[b][j] = gap[b] . weight[j] + bias[j]  (48 outputs)
            if (tid < BATCH * 3) {
                int b = tid / 3, j = tid % 3;
                const float4* g4 = reinterpret_cast<const float4*>(gap + b * KDIM);
                const float4* w4 = reinterpret_cast<const float4*>(weight + j * KDIM);
                float acc = 0.f;
#pragma unroll 8
                for (int k = 0; k < KDIM / 4; ++k) {
                    float4 a = g4[k], w = w4[k];
                    acc += a.x * w.x + a.y * w.y + a.z * w.z + a.w * w.w;
                }
                dout[OUT_FC + tid] = acc + bias[j];
            }
        }
    }

    // self-reset: last block out restores counters for the next graph replay.
    __syncthreads();
    if (tid == 0) {
        __threadfence();
        int d = atomicAdd(&g_done, 1);
        if (d == GRID_MAIN - 1) {
            g_ctr  = 0;
            g_done = 0;
            __threadfence();
        }
    }
}

extern "C" void kernel_launch(void* const* d_in, const int* in_sizes, int n_in,
                              void* d_out, int out_size)
{
    const float* gap    = (const float*)d_in[0];
    const float* out1   = (const float*)d_in[1];
    const float* out2   = (const float*)d_in[2];
    const float* out3   = (const float*)d_in[3];
    const float* weight = (const float*)d_in[4];
    const float* bias   = (const float*)d_in[5];
    float* dout = (float*)d_out;

    fused_all_kernel<<<GRID_MAIN, 256>>>(gap, out1, out2, out3, weight, bias, dout);
}